// round 1
// baseline (speedup 1.0000x reference)
#include <cuda_runtime.h>
#include <cstdint>

// Conv4D with separable rank-1 kernel (K ⊗ K), VALID padding.
// input  : (8192, 8, 8, 8, 8) fp32
// kernel : (3, 3) fp32
// output : (8192, 6, 6, 6, 6) fp32
//
// Separable two-pass in shared memory:
//   pass 1: correlate dims (3,4)  -> T[8][8][6][6]  (2304 floats)
//   pass 2: correlate dims (1,2)  -> out[6][6][6][6] (1296 floats)

#define THREADS 256

__global__ __launch_bounds__(THREADS, 8)
void conv4d_sep_kernel(const float* __restrict__ in,
                       const float* __restrict__ ker,
                       float* __restrict__ out)
{
    __shared__ float s_in[4096];        // 8*8*8*8   = 16 KB
    __shared__ float s_t[8 * 8 * 36];   // 8*8*6*6   = 9 KB

    const int b   = blockIdx.x;
    const int tid = threadIdx.x;

    // Broadcast the 9 kernel taps into registers (L1/L2-cached after wave 1).
    float k[9];
#pragma unroll
    for (int i = 0; i < 9; i++) k[i] = __ldg(&ker[i]);

    // Bulk-load this batch's 4096 floats: 256 threads x 4 float4 = 16 KB, coalesced.
    {
        const float4* gin  = reinterpret_cast<const float4*>(in + (size_t)b * 4096);
        float4*       sin4 = reinterpret_cast<float4*>(s_in);
#pragma unroll
        for (int i = 0; i < 4; i++)
            sin4[tid + i * THREADS] = gin[tid + i * THREADS];
    }
    __syncthreads();

    // ---- Pass 1: correlate over (d3, d4): 8x8 -> 6x6 per (d1,d2) plane ----
    // T[a][b2][e3][e4] = sum_{kk,ll} in[a][b2][e3+kk][e4+ll] * K[kk][ll]
    // 2304 elements = 9 per thread.
#pragma unroll
    for (int r = 0; r < 9; r++) {
        const int idx = tid + r * THREADS;          // 0..2303
        const int e4  = idx % 6;
        const int e3  = (idx / 6) % 6;
        const int ab  = idx / 36;                   // (d1*8 + d2), 0..63
        const float* base = &s_in[ab * 64 + e3 * 8 + e4];
        float acc = 0.0f;
#pragma unroll
        for (int kk = 0; kk < 3; kk++)
#pragma unroll
            for (int ll = 0; ll < 3; ll++)
                acc = fmaf(base[kk * 8 + ll], k[kk * 3 + ll], acc);
        s_t[idx] = acc;
    }
    __syncthreads();

    // ---- Pass 2: correlate over (d1, d2): 8x8 -> 6x6 ----
    // out[e1][e2][e3][e4] = sum_{i,j} T[e1+i][e2+j][e3][e4] * K[i][j]
    // 1296 outputs; contiguous coalesced stores.
    float* gout = out + (size_t)b * 1296;
    for (int idx = tid; idx < 1296; idx += THREADS) {
        const int e34 = idx % 36;                   // e3*6 + e4
        const int e2  = (idx / 36) % 6;
        const int e1  = idx / 216;
        const float* base = &s_t[(e1 * 8 + e2) * 36 + e34];
        float acc = 0.0f;
#pragma unroll
        for (int i = 0; i < 3; i++)
#pragma unroll
            for (int j = 0; j < 3; j++)
                acc = fmaf(base[(i * 8 + j) * 36], k[i * 3 + j], acc);
        gout[idx] = acc;
    }
}

extern "C" void kernel_launch(void* const* d_in, const int* in_sizes, int n_in,
                              void* d_out, int out_size)
{
    const float* in  = (const float*)d_in[0];   // (8192,8,8,8,8) fp32
    const float* ker = (const float*)d_in[1];   // (3,3) fp32
    float*       out = (float*)d_out;           // (8192,6,6,6,6) fp32

    const int batches = in_sizes[0] / 4096;     // 8192
    conv4d_sep_kernel<<<batches, THREADS>>>(in, ker, out);
}

// round 2
// speedup vs baseline: 1.5238x; 1.5238x over previous
#include <cuda_runtime.h>
#include <cstdint>

// Conv4D with separable rank-1 kernel (K ⊗ K), VALID padding.
// input  : (8192, 8, 8, 8, 8) fp32
// kernel : (3, 3) fp32
// output : (8192, 6, 6, 6, 6) fp32
//
// Two-pass separable with register sliding windows:
//   pass 1: correlate dims (3,4), reading input straight from global (L1-hot):
//           unit (ab, e3) loads 3x8 floats -> 6 outputs   (384 units/batch)
//   pass 2: correlate dims (1,2) out of smem T:
//           unit (e1, e34) loads 3x8 floats -> 6 outputs  (216 units/batch)

#define THREADS 128

__global__ __launch_bounds__(THREADS)
void conv4d_sep2_kernel(const float* __restrict__ in,
                        const float* __restrict__ ker,
                        float* __restrict__ out)
{
    __shared__ float s_t[8 * 8 * 36];   // T[a][b2][e3*6+e4], 9.2 KB

    const int b   = blockIdx.x;
    const int tid = threadIdx.x;

    float k[9];
#pragma unroll
    for (int i = 0; i < 9; i++) k[i] = __ldg(&ker[i]);

    const float* gin = in + (size_t)b * 4096;

    // ---- Pass 1: 384 units, exactly 3 per thread ----
    // unit u -> ab = u/6 (which 8x8 plane), e3 = u%6 (output row)
    // loads rows e3..e3+2 (8 floats each) from global, slides window for 6 e4.
#pragma unroll
    for (int p = 0; p < 3; p++) {
        const int u  = tid + p * THREADS;     // 0..383
        const int ab = u / 6;
        const int e3 = u - ab * 6;

        const float4* base =
            reinterpret_cast<const float4*>(gin + ab * 64 + e3 * 8);

        float r[3][8];
#pragma unroll
        for (int kk = 0; kk < 3; kk++) {
            float4 lo = __ldg(&base[kk * 2 + 0]);
            float4 hi = __ldg(&base[kk * 2 + 1]);
            r[kk][0] = lo.x; r[kk][1] = lo.y; r[kk][2] = lo.z; r[kk][3] = lo.w;
            r[kk][4] = hi.x; r[kk][5] = hi.y; r[kk][6] = hi.z; r[kk][7] = hi.w;
        }

        float acc[6];
#pragma unroll
        for (int e4 = 0; e4 < 6; e4++) acc[e4] = 0.0f;
#pragma unroll
        for (int kk = 0; kk < 3; kk++)
#pragma unroll
            for (int ll = 0; ll < 3; ll++) {
                const float kv = k[kk * 3 + ll];
#pragma unroll
                for (int e4 = 0; e4 < 6; e4++)
                    acc[e4] = fmaf(r[kk][e4 + ll], kv, acc[e4]);
            }

        float* t = &s_t[u * 6];               // = ab*36 + e3*6, contiguous
#pragma unroll
        for (int e4 = 0; e4 < 6; e4++) t[e4] = acc[e4];
    }
    __syncthreads();

    // ---- Pass 2: 216 units ----
    // unit v -> e1 = v/36, e34 = v%36.
    // loads T[e1+i][j'][e34] for i=0..2, j'=0..7 (stride-36 scalar, conflict-free:
    // consecutive lanes hit consecutive e34 -> consecutive banks), 6 outputs along e2.
    float* gout = out + (size_t)b * 1296;
    for (int v = tid; v < 216; v += THREADS) {
        const int e1  = v / 36;
        const int e34 = v - e1 * 36;

        float t[3][8];
#pragma unroll
        for (int i = 0; i < 3; i++)
#pragma unroll
            for (int j = 0; j < 8; j++)
                t[i][j] = s_t[((e1 + i) * 8 + j) * 36 + e34];

        float acc[6];
#pragma unroll
        for (int e2 = 0; e2 < 6; e2++) acc[e2] = 0.0f;
#pragma unroll
        for (int i = 0; i < 3; i++)
#pragma unroll
            for (int j = 0; j < 3; j++) {
                const float kv = k[i * 3 + j];
#pragma unroll
                for (int e2 = 0; e2 < 6; e2++)
                    acc[e2] = fmaf(t[i][e2 + j], kv, acc[e2]);
            }

#pragma unroll
        for (int e2 = 0; e2 < 6; e2++)
            gout[e1 * 216 + e2 * 36 + e34] = acc[e2];
    }
}

extern "C" void kernel_launch(void* const* d_in, const int* in_sizes, int n_in,
                              void* d_out, int out_size)
{
    const float* in  = (const float*)d_in[0];   // (8192,8,8,8,8) fp32
    const float* ker = (const float*)d_in[1];   // (3,3) fp32
    float*       out = (float*)d_out;           // (8192,6,6,6,6) fp32

    const int batches = in_sizes[0] / 4096;     // 8192
    conv4d_sep2_kernel<<<batches, THREADS>>>(in, ker, out);
}

// round 4
// speedup vs baseline: 1.7391x; 1.1413x over previous
#include <cuda_runtime.h>
#include <cstdint>

// Conv4D with separable rank-1 kernel (K ⊗ K), VALID padding.
// input  : (8192, 8, 8, 8, 8) fp32 -> output (8192, 6, 6, 6, 6) fp32
//
// Three-stage, bank-exact shared-memory design (one CTA per batch, 128 thr):
//   stage : gmem -> smem, coalesced scalar LDG + conflict-free STS (65-pad)
//   pass1 : conv over (d3,d4); lanes along plane index ab (65 = 1 mod 32 =>
//           conflict-free LDS), rolling 3-row register window, half-plane/thread
//   pass2 : conv over (d1,d2) from 37-padded T planes; lanes along e34
//           (conflict-free LDS, coalesced STG)

#define THREADS 128

__global__ __launch_bounds__(THREADS, 8)
void conv4d_sep3_kernel(const float* __restrict__ in,
                        const float* __restrict__ ker,
                        float* __restrict__ out)
{
    __shared__ float s_in[64 * 65];   // input planes, padded: 16,640 B
    __shared__ float s_t [64 * 37];   // T planes, padded:      9,472 B

    const int b   = blockIdx.x;
    const int tid = threadIdx.x;

    float k[9];
#pragma unroll
    for (int i = 0; i < 9; i++) k[i] = __ldg(&ker[i]);

    const float* gin = in + (size_t)b * 4096;

    // ---- Stage: 4096 floats, coalesced scalar LDG, conflict-free STS ----
    {
        const int w  = tid & 63;       // word within plane
        const int p0 = tid >> 6;       // 0 or 1
#pragma unroll
        for (int i = 0; i < 32; i++) {
            const int plane = p0 + 2 * i;
            s_in[plane * 65 + w] = __ldg(gin + plane * 64 + w);
        }
    }
    __syncthreads();

    // ---- Pass 1: correlate (d3,d4). Thread = (half, ab): e3 in half*3..half*3+2
    // Lanes within a warp hit 32 distinct planes -> LDS bank = (ab + c) % 32,
    // conflict-free. Rolling 3-row window: 5 rows loaded -> 18 T outputs.
    {
        const int half = tid >> 6;               // 0 or 1
        const int ab   = tid & 63;
        const float* sp = &s_in[ab * 65 + half * 24];  // rows half*3 ..
        float*       tp = &s_t [ab * 37 + half * 18];

        float r[3][8];
#pragma unroll
        for (int c = 0; c < 8; c++) { r[0][c] = sp[c]; r[1][c] = sp[8 + c]; }

#pragma unroll
        for (int e3 = 0; e3 < 3; e3++) {
#pragma unroll
            for (int c = 0; c < 8; c++)
                r[(e3 + 2) % 3][c] = sp[(e3 + 2) * 8 + c];

            float acc[6];
#pragma unroll
            for (int e4 = 0; e4 < 6; e4++) acc[e4] = 0.0f;
#pragma unroll
            for (int kk = 0; kk < 3; kk++) {
                const float* row = r[(e3 + kk) % 3];
#pragma unroll
                for (int ll = 0; ll < 3; ll++) {
                    const float kv = k[kk * 3 + ll];
#pragma unroll
                    for (int e4 = 0; e4 < 6; e4++)
                        acc[e4] = fmaf(row[e4 + ll], kv, acc[e4]);
                }
            }
#pragma unroll
            for (int e4 = 0; e4 < 6; e4++) tp[e3 * 6 + e4] = acc[e4];
        }
    }
    __syncthreads();

    // ---- Pass 2: correlate (d1,d2). Unit v = (e1, e34), lanes along e34:
    // conflict-free LDS (stride-1 within warp), coalesced contiguous STG.
    float* gout = out + (size_t)b * 1296;
#pragma unroll
    for (int p = 0; p < 2; p++) {
        const int v = tid + p * THREADS;        // 0..255; active if < 216
        if (v < 216) {
            const int e1  = v / 36;
            const int e34 = v - e1 * 36;

            float t[3][8];
#pragma unroll
            for (int i = 0; i < 3; i++)
#pragma unroll
                for (int j = 0; j < 8; j++)
                    t[i][j] = s_t[((e1 + i) * 8 + j) * 37 + e34];

            float acc[6];
#pragma unroll
            for (int e2 = 0; e2 < 6; e2++) acc[e2] = 0.0f;
#pragma unroll
            for (int i = 0; i < 3; i++)
#pragma unroll
                for (int j = 0; j < 3; j++) {
                    const float kv = k[i * 3 + j];
#pragma unroll
                    for (int e2 = 0; e2 < 6; e2++)
                        acc[e2] = fmaf(t[i][e2 + j], kv, acc[e2]);
                }

#pragma unroll
            for (int e2 = 0; e2 < 6; e2++)
                gout[e1 * 216 + e2 * 36 + e34] = acc[e2];
        }
    }
}

extern "C" void kernel_launch(void* const* d_in, const int* in_sizes, int n_in,
                              void* d_out, int out_size)
{
    const float* in  = (const float*)d_in[0];   // (8192,8,8,8,8) fp32
    const float* ker = (const float*)d_in[1];   // (3,3) fp32
    float*       out = (float*)d_out;           // (8192,6,6,6,6) fp32

    const int batches = in_sizes[0] / 4096;     // 8192
    conv4d_sep3_kernel<<<batches, THREADS>>>(in, ker, out);
}